// round 17
// baseline (speedup 1.0000x reference)
#include <cuda_runtime.h>
#include <cuda_fp16.h>
#include <math.h>
#include <stdint.h>

// Problem constants
#define Bn   16
#define Cc   256
#define Nn   4096
#define Hh   4
#define Dd   64
#define O3   768
#define HID  256
#define SCALE 0.125f

// Scratch (pure fp16 operand pipeline, fp32 accumulation everywhere)
__device__ __half g_xh[(size_t)Bn * Cc * Nn];     // x fp16
__device__ __half g_wh[O3 * Cc];                  // w_qkv fp16
__device__ __half g_qh[(size_t)Bn * HID * Nn];    // q softmaxed fp16
__device__ __half g_kh[(size_t)Bn * HID * Nn];    // k fp16 (softmaxed in place)
__device__ __half g_vh[(size_t)Bn * HID * Nn];    // v fp16
__device__ float  g_ctxp[(size_t)Bn * Hh * 16 * Dd * Dd];
__device__ __half g_w2h[(size_t)Bn * HID * HID];  // w_out @ ctx^T fp16

// ===========================================================================
// Helpers
// ===========================================================================
__device__ __forceinline__ uint32_t smem_u32(const void* p) {
    uint32_t a;
    asm("{ .reg .u64 t; cvta.to.shared.u64 t, %1; cvt.u32.u64 %0, t; }" : "=r"(a) : "l"(p));
    return a;
}
__device__ __forceinline__ void mma16(float* d, const uint32_t* a, const uint32_t* b) {
    asm volatile(
        "mma.sync.aligned.m16n8k16.row.col.f32.f16.f16.f32 "
        "{%0,%1,%2,%3},{%4,%5,%6,%7},{%8,%9},{%0,%1,%2,%3};"
        : "+f"(d[0]), "+f"(d[1]), "+f"(d[2]), "+f"(d[3])
        : "r"(a[0]), "r"(a[1]), "r"(a[2]), "r"(a[3]), "r"(b[0]), "r"(b[1]));
}
#define LDM_X4(r, addr) \
    asm volatile("ldmatrix.sync.aligned.m8n8.x4.shared.b16 {%0,%1,%2,%3}, [%4];" \
        : "=r"((r)[0]), "=r"((r)[1]), "=r"((r)[2]), "=r"((r)[3]) : "r"(addr))
#define LDM_X4_T(r, addr) \
    asm volatile("ldmatrix.sync.aligned.m8n8.x4.trans.shared.b16 {%0,%1,%2,%3}, [%4];" \
        : "=r"((r)[0]), "=r"((r)[1]), "=r"((r)[2]), "=r"((r)[3]) : "r"(addr))
#define CP_ASYNC16(dst, src) \
    asm volatile("cp.async.cg.shared.global [%0], [%1], 16;" :: "r"(dst), "l"(src))
#define CP_COMMIT() asm volatile("cp.async.commit_group;" ::: "memory")
#define CP_WAIT(n)  asm volatile("cp.async.wait_group %0;" :: "n"(n) : "memory")

// ===========================================================================
// fp32 -> fp16 conversion
// ===========================================================================
__global__ void half_kernel(const float* __restrict__ src, __half* __restrict__ h, int n4)
{
    int i = blockIdx.x * blockDim.x + threadIdx.x;
    if (i >= n4) return;
    float4 v = *(const float4*)(src + (size_t)i * 4);
    *(half2*)(h + (size_t)i * 4)     = __halves2half2(__float2half_rn(v.x), __float2half_rn(v.y));
    *(half2*)(h + (size_t)i * 4 + 2) = __halves2half2(__float2half_rn(v.z), __float2half_rn(v.w));
}

// ===========================================================================
// fused_gemm: plain fp16 GEMM, fp32 accumulate.
// CTA tile 128(m) x 256(n), warp tile 64x64 (8 warps = 2m x 4n).
// K=256, BK=64 (4 slices), 3-stage cp.async ring, one barrier per slice.
// 1 CTA/SM (registers ~195). MMA:LDSM ratio 4.0, 32-deep MMA bursts.
// mode 0 (GEMM1): y 0-1 q (fused softmax_d -> fp16), y 2-3 k, y 4-5 v.
// mode 1 (GEMM2): fp32 out + bias.
// ===========================================================================
#define PA_B 144                     // A pitch bytes (64 halves + 16 pad)
#define PB_B 528                     // B pitch bytes (256 halves + 16 pad)
#define A_ST (128 * PA_B)            // 18432
#define B_ST (64 * PB_B)             // 33792
#define STG  (A_ST + B_ST)           // 52224
#define FG_SMEM (3 * STG)            // 156672 -> 1 CTA/SM

__global__ void __launch_bounds__(256, 1)
fused_gemm(const __half* __restrict__ Ah, size_t aStride,
           const __half* __restrict__ Bh, size_t bStride,
           int mode, const float* __restrict__ bias, float* __restrict__ outF)
{
    extern __shared__ char smem[];
    const uint32_t sb = smem_u32(smem);
    const int tid  = threadIdx.x;
    const int wid  = tid >> 5;
    const int lane = tid & 31;
    const int wm   = (wid >> 2) * 64;     // 2 m-warps
    const int wn   = (wid & 3) * 64;      // 4 n-warps (64 wide each)
    const int y    = blockIdx.y;
    const int mBlk = y * 128;
    const int nBlk = blockIdx.x * 256;
    const int z    = blockIdx.z;

    const __half* Ag = Ah + (size_t)z * aStride + (size_t)mBlk * 256;
    const __half* Bg = Bh + (size_t)z * bStride + nBlk;

    float acc[4][8][4];
    #pragma unroll
    for (int i = 0; i < 4; i++)
        #pragma unroll
        for (int j = 0; j < 8; j++)
            #pragma unroll
            for (int r = 0; r < 4; r++) acc[i][j][r] = 0.f;

    auto issue = [&](int s, int buf) {
        const int kk = s * 64;
        const uint32_t st = sb + buf * STG;
        #pragma unroll
        for (int p = 0; p < 4; p++) {            // A: 128 rows x 8 chunks
            int id = tid + p * 256;
            int m = id >> 3, ch = id & 7;
            size_t go = (size_t)m * 256 + kk + ch * 8;
            CP_ASYNC16(st + m * PA_B + ch * 16, Ag + go);
        }
        #pragma unroll
        for (int p = 0; p < 8; p++) {            // B: 64 rows x 32 chunks
            int id = tid + p * 256;
            int r = id >> 5, ch = id & 31;
            size_t go = (size_t)(kk + r) * Nn + ch * 8;
            CP_ASYNC16(st + A_ST + r * PB_B + ch * 16, Bg + go);
        }
    };

    const int lr = lane & 15;
    const int lc = (lane >> 4) & 1;

    auto compute = [&](int buf) {
        const uint32_t aHb = sb + buf * STG;
        const uint32_t bHb = aHb + A_ST;
        #pragma unroll
        for (int ks = 0; ks < 4; ks++) {
            uint32_t bh[4][4];
            #pragma unroll
            for (int fnp = 0; fnp < 4; fnp++) {
                uint32_t off = (uint32_t)(ks * 16 + lr) * PB_B
                             + (uint32_t)(wn + fnp * 16 + lc * 8) * 2;
                LDM_X4_T(bh[fnp], bHb + off);
            }
            uint32_t ah[4][4];
            #pragma unroll
            for (int fm = 0; fm < 4; fm++) {
                uint32_t off = (uint32_t)(wm + fm * 16 + lr) * PA_B
                             + (uint32_t)(ks * 16 + lc * 8) * 2;
                LDM_X4(ah[fm], aHb + off);
            }
            #pragma unroll
            for (int fm = 0; fm < 4; fm++)
                #pragma unroll
                for (int fn = 0; fn < 8; fn++)
                    mma16(acc[fm][fn], ah[fm], &bh[fn >> 1][(fn & 1) * 2]);
        }
    };

    issue(0, 0); CP_COMMIT();
    issue(1, 1); CP_COMMIT();
    #pragma unroll 1
    for (int s = 0; s < 4; s++) {
        if (s < 3) { CP_WAIT(1); } else { CP_WAIT(0); }
        __syncthreads();
        if (s + 2 < 4) { issue(s + 2, (s + 2) % 3); CP_COMMIT(); }
        compute(s % 3);
    }

    // ------------------------------ epilogues ------------------------------
    if (mode == 1) {
        float* Cg = outF + (size_t)z * HID * Nn;
        #pragma unroll
        for (int fm = 0; fm < 4; fm++) {
            int row = mBlk + wm + fm * 16 + (lane >> 2);
            float b0 = bias[row], b8 = bias[row + 8];
            #pragma unroll
            for (int fn = 0; fn < 8; fn++) {
                int col = nBlk + wn + fn * 8 + (lane & 3) * 2;
                float2 v0 = { acc[fm][fn][0] + b0, acc[fm][fn][1] + b0 };
                float2 v1 = { acc[fm][fn][2] + b8, acc[fm][fn][3] + b8 };
                *(float2*)&Cg[(size_t)row * Nn + col]       = v0;
                *(float2*)&Cg[(size_t)(row + 8) * Nn + col] = v1;
            }
        }
        return;
    }

    if (y >= 2) {    // K or V: plain fp16
        __half* Oh = (y < 4 ? g_kh : g_vh)
                   + ((size_t)z * HID + mBlk - (y < 4 ? 256 : 512)) * Nn;
        #pragma unroll
        for (int fm = 0; fm < 4; fm++) {
            int row = wm + fm * 16 + (lane >> 2);
            #pragma unroll
            for (int fn = 0; fn < 8; fn++) {
                int col = nBlk + wn + fn * 8 + (lane & 3) * 2;
                *(half2*)&Oh[(size_t)row * Nn + col] =
                    __halves2half2(__float2half_rn(acc[fm][fn][0]),
                                   __float2half_rn(acc[fm][fn][1]));
                *(half2*)&Oh[(size_t)(row + 8) * Nn + col] =
                    __halves2half2(__float2half_rn(acc[fm][fn][2]),
                                   __float2half_rn(acc[fm][fn][3]));
            }
        }
        return;
    }

    // Q: fused softmax over d (2 heads per 128-row tile), x SCALE, fp16 out
    {
        float* S    = (float*)smem;                        // [128][260] = 133120 B
        float* cInv = (float*)(smem + 128 * 260 * 4);      // [512]
        __syncthreads();
        #pragma unroll
        for (int fm = 0; fm < 4; fm++) {
            int row = wm + fm * 16 + (lane >> 2);
            #pragma unroll
            for (int fn = 0; fn < 8; fn++) {
                int col = wn + fn * 8 + (lane & 3) * 2;
                *(float2*)&S[row * 260 + col]       = make_float2(acc[fm][fn][0], acc[fm][fn][1]);
                *(float2*)&S[(row + 8) * 260 + col] = make_float2(acc[fm][fn][2], acc[fm][fn][3]);
            }
        }
        __syncthreads();

        // 512 column-tasks (2 heads x 256 cols); each thread does 2
        #pragma unroll
        for (int t = tid; t < 512; t += 256) {
            int colI = t & 255;
            int hf   = t >> 8;
            float mx = -INFINITY;
            #pragma unroll 4
            for (int r = 0; r < 64; r++)
                mx = fmaxf(mx, S[(hf * 64 + r) * 260 + colI]);
            float sum = 0.f;
            #pragma unroll 4
            for (int r = 0; r < 64; r++) {
                float e = __expf(S[(hf * 64 + r) * 260 + colI] - mx);
                S[(hf * 64 + r) * 260 + colI] = e;
                sum += e;
            }
            cInv[t] = SCALE / sum;
        }
        __syncthreads();

        __half* Qh = g_qh + ((size_t)z * HID + mBlk) * Nn + nBlk;
        int c2   = (tid & 127) * 2;
        int rgrp = tid >> 7;             // 0..1
        #pragma unroll 4
        for (int rr = 0; rr < 64; rr++) {
            int row = rgrp * 64 + rr;
            int ci  = ((row >> 6) << 8) | c2;
            float2 v = *(float2*)&S[row * 260 + c2];
            *(half2*)&Qh[(size_t)row * Nn + c2] =
                __halves2half2(__float2half_rn(v.x * cInv[ci]),
                               __float2half_rn(v.y * cInv[ci + 1]));
        }
    }
}

// ===========================================================================
// Softmax over n on k: fp16 in/out, uint4-vectorized, shuffle reductions.
// ===========================================================================
__global__ void softmax_k_kernel()
{
    int row = blockIdx.x;
    size_t base = (size_t)row * Nn;
    __shared__ float red[8];
    const int tid  = threadIdx.x;
    const int lane = tid & 31;
    const int wrp  = tid >> 5;

    uint4 u[2];
    float v[16];
    #pragma unroll
    for (int i = 0; i < 2; i++) {
        u[i] = *(const uint4*)(g_kh + base + (size_t)(tid + i * 256) * 8);
        const __half2* hp = (const __half2*)&u[i];
        #pragma unroll
        for (int j = 0; j < 4; j++) {
            float2 f = __half22float2(hp[j]);
            v[i * 8 + j * 2]     = f.x;
            v[i * 8 + j * 2 + 1] = f.y;
        }
    }
    float mx = -INFINITY;
    #pragma unroll
    for (int i = 0; i < 16; i++) mx = fmaxf(mx, v[i]);
    #pragma unroll
    for (int o = 16; o; o >>= 1) mx = fmaxf(mx, __shfl_xor_sync(0xffffffffu, mx, o));
    if (lane == 0) red[wrp] = mx;
    __syncthreads();
    mx = red[0];
    #pragma unroll
    for (int i = 1; i < 8; i++) mx = fmaxf(mx, red[i]);
    __syncthreads();

    float sum = 0.f;
    #pragma unroll
    for (int i = 0; i < 16; i++) { v[i] = __expf(v[i] - mx); sum += v[i]; }
    #pragma unroll
    for (int o = 16; o; o >>= 1) sum += __shfl_xor_sync(0xffffffffu, sum, o);
    if (lane == 0) red[wrp] = sum;
    __syncthreads();
    sum = 0.f;
    #pragma unroll
    for (int i = 0; i < 8; i++) sum += red[i];
    float inv = 1.f / sum;

    #pragma unroll
    for (int i = 0; i < 2; i++) {
        __half2* hp = (__half2*)&u[i];
        #pragma unroll
        for (int j = 0; j < 4; j++)
            hp[j] = __floats2half2_rn(v[i * 8 + j * 2] * inv, v[i * 8 + j * 2 + 1] * inv);
        *(uint4*)(g_kh + base + (size_t)(tid + i * 256) * 8) = u[i];
    }
}

// ===========================================================================
// Context partials (16 n-chunks of 256): ctxp[bh][p][d][e] = sum k[d,n]v[e,n]
// ===========================================================================
#define PK_B 272
#define CT_B (64 * PK_B)
#define CTX_SMEM_BYTES (2 * CT_B)     // 34816

__global__ void __launch_bounds__(128, 4)
context_part()
{
    extern __shared__ char smem[];
    const uint32_t sb = smem_u32(smem);
    int bh = blockIdx.x;
    int p  = blockIdx.y;
    int b = bh >> 2, h = bh & 3;
    const __half* Kh = g_kh + ((size_t)b * HID + h * Dd) * Nn;
    const __half* Vh = g_vh + ((size_t)b * HID + h * Dd) * Nn;

    const int tid  = threadIdx.x;
    const int wid  = tid >> 5;
    const int lane = tid & 31;
    const int wm = (wid >> 1) * 32;
    const int wn = (wid & 1) * 32;

    float acc[2][4][4];
    #pragma unroll
    for (int i = 0; i < 2; i++)
        #pragma unroll
        for (int j = 0; j < 4; j++)
            #pragma unroll
            for (int r = 0; r < 4; r++) acc[i][j][r] = 0.f;

    const int lr = lane & 15;
    const int lc = (lane >> 4) & 1;
    const uint32_t kHb = sb;
    const uint32_t vHb = kHb + CT_B;

    #pragma unroll 1
    for (int sl = 0; sl < 2; sl++) {
        const int nn = p * 256 + sl * 128;
        __syncthreads();
        #pragma unroll
        for (int q = 0; q < 8; q++) {
            int id = tid + q * 128;
            int row = id >> 4, ch = id & 15;
            size_t go = (size_t)row * Nn + nn + ch * 8;
            uint32_t off = row * PK_B + ch * 16;
            CP_ASYNC16(kHb + off, Kh + go);
            CP_ASYNC16(vHb + off, Vh + go);
        }
        CP_COMMIT();
        CP_WAIT(0);
        __syncthreads();

        #pragma unroll
        for (int ks = 0; ks < 8; ks++) {
            uint32_t bhf[2][4];
            #pragma unroll
            for (int fnp = 0; fnp < 2; fnp++) {
                uint32_t off = (uint32_t)(wn + fnp * 16 + lc * 8 + (lane & 7)) * PK_B
                             + (uint32_t)(ks * 32 + ((lane >> 3) & 1) * 16);
                LDM_X4(bhf[fnp], vHb + off);
            }
            uint32_t ah[2][4];
            #pragma unroll
            for (int fm = 0; fm < 2; fm++) {
                uint32_t off = (uint32_t)(wm + fm * 16 + lr) * PK_B
                             + (uint32_t)(ks * 32 + lc * 16);
                LDM_X4(ah[fm], kHb + off);
            }
            #pragma unroll
            for (int fm = 0; fm < 2; fm++)
                #pragma unroll
                for (int fn = 0; fn < 4; fn++)
                    mma16(acc[fm][fn], ah[fm], &bhf[fn >> 1][(fn & 1) * 2]);
        }
    }

    float* dst = g_ctxp + ((size_t)bh * 16 + p) * (Dd * Dd);
    #pragma unroll
    for (int fm = 0; fm < 2; fm++) {
        int d0 = wm + fm * 16 + (lane >> 2);
        #pragma unroll
        for (int fn = 0; fn < 4; fn++) {
            int e0 = wn + fn * 8 + (lane & 3) * 2;
            dst[d0 * Dd + e0]           = acc[fm][fn][0];
            dst[d0 * Dd + e0 + 1]       = acc[fm][fn][1];
            dst[(d0 + 8) * Dd + e0]     = acc[fm][fn][2];
            dst[(d0 + 8) * Dd + e0 + 1] = acc[fm][fn][3];
        }
    }
}

// ===========================================================================
// W2[b][c][h*64+d] = sum_e w_out[c][h*64+e] * ctx[bh][d][e]; fp16 out.
// ===========================================================================
__global__ void w2_kernel(const float* __restrict__ w_out)
{
    int bh = blockIdx.x;
    int b = bh >> 2, h = bh & 3;
    __shared__ float ctx[Dd * Dd];
    const int tid = threadIdx.x;

    for (int i = tid; i < Dd * Dd; i += 256) {
        float s = 0.f;
        #pragma unroll
        for (int p = 0; p < 16; p++)
            s += g_ctxp[((size_t)bh * 16 + p) * (Dd * Dd) + i];
        ctx[i] = s;
    }
    __syncthreads();

    int c = tid;
    float w[Dd];
    #pragma unroll
    for (int e = 0; e < Dd; e++) w[e] = w_out[c * HID + h * Dd + e];
    #pragma unroll 4
    for (int d = 0; d < Dd; d++) {
        float s = 0.f;
        #pragma unroll
        for (int e = 0; e < Dd; e++) s = fmaf(w[e], ctx[d * Dd + e], s);
        g_w2h[((size_t)b * HID + c) * HID + h * Dd + d] = __float2half_rn(s);
    }
}

// ===========================================================================
extern "C" void kernel_launch(void* const* d_in, const int* in_sizes, int n_in,
                              void* d_out, int out_size)
{
    const float* x     = (const float*)d_in[0];
    const float* w_qkv = (const float*)d_in[1];
    const float* w_out = (const float*)d_in[2];
    const float* b_out = (const float*)d_in[3];
    float* out = (float*)d_out;

    __half *xh, *wh, *qh, *w2h;
    cudaGetSymbolAddress((void**)&xh, g_xh);
    cudaGetSymbolAddress((void**)&wh, g_wh);
    cudaGetSymbolAddress((void**)&qh, g_qh);
    cudaGetSymbolAddress((void**)&w2h, g_w2h);

    static int init_done = 0;
    if (!init_done) {
        cudaFuncSetAttribute(fused_gemm, cudaFuncAttributeMaxDynamicSharedMemorySize, FG_SMEM);
        cudaFuncSetAttribute(context_part, cudaFuncAttributeMaxDynamicSharedMemorySize, CTX_SMEM_BYTES);
        init_done = 1;
    }

    // 0) x, w_qkv -> fp16
    {
        int n4 = (Bn * Cc * Nn) / 4;
        half_kernel<<<(n4 + 255) / 256, 256>>>(x, xh, n4);
        int w4 = (O3 * Cc) / 4;
        half_kernel<<<(w4 + 255) / 256, 256>>>(w_qkv, wh, w4);
    }
    // 1) GEMM1: single launch, y selects q/k/v epilogue
    {
        dim3 grid(Nn / 256, O3 / 128, Bn);
        fused_gemm<<<grid, 256, FG_SMEM>>>(wh, 0, xh, (size_t)Cc * Nn,
                                           0, nullptr, nullptr);
    }
    // 2) softmax over n on k (in place, fp16)
    softmax_k_kernel<<<Bn * HID, 256>>>();
    // 3) context partials
    {
        dim3 gridc(Bn * Hh, 16);
        context_part<<<gridc, 128, CTX_SMEM_BYTES>>>();
    }
    // 4) W2
    w2_kernel<<<Bn * Hh, 256>>>(w_out);
    // 5) GEMM2: out = W2 @ q + bias
    {
        dim3 grid2(Nn / 256, HID / 128, Bn);
        fused_gemm<<<grid2, 256, FG_SMEM>>>(w2h, (size_t)HID * HID,
                                            qh, (size_t)HID * Nn,
                                            1, b_out, out);
    }
}